// round 13
// baseline (speedup 1.0000x reference)
#include <cuda_runtime.h>
#include <cuda_bf16.h>
#include <cuda_fp16.h>
#include <math.h>

#define MAXN 50000
#define MAXE 800000
#define HD 128
#define NHEAD 8
#define TS 136   // smem tile stride in bf16 elements (272B rows: conflict-free ldmatrix)

__device__ float  g_Q[(size_t)MAXN * HD];
__device__ __half g_Kh[(size_t)MAXN * HD];
__device__ __half g_Vh[(size_t)MAXN * HD];
__device__ unsigned short g_h_hi[(size_t)MAXN * HD];
__device__ unsigned short g_h_lo[(size_t)MAXN * HD];
__device__ int    g_count[MAXN];
__device__ int    g_start[MAXN];
__device__ int    g_cursor[MAXN];
__device__ int    g_csr_src[MAXE];
__device__ int    g_total[1];

// ---------------------------------------------------------------------------
// Prepass: split h (fp32) into bf16 hi/lo arrays ONCE (was done 3x per tile
// inside qkv). qkv then loads bf16 directly via cp.async with no ALU work.
// ---------------------------------------------------------------------------
__global__ __launch_bounds__(256) void split_h_kernel(
    const float* __restrict__ h, int total4)
{
    int i = blockIdx.x * blockDim.x + threadIdx.x;
    if (i >= total4) return;
    float4 v = *(const float4*)&h[(size_t)i * 4];
    float vv[4] = {v.x, v.y, v.z, v.w};
    unsigned short hs[4], ls[4];
    #pragma unroll
    for (int j = 0; j < 4; j++) {
        __nv_bfloat16 hb = __float2bfloat16(vv[j]);
        float lf = vv[j] - __bfloat162float(hb);
        __nv_bfloat16 lb = __float2bfloat16(lf);
        hs[j] = __bfloat16_as_ushort(hb);
        ls[j] = __bfloat16_as_ushort(lb);
    }
    uint2 ph, pl;
    ph.x = (unsigned)hs[0] | ((unsigned)hs[1] << 16);
    ph.y = (unsigned)hs[2] | ((unsigned)hs[3] << 16);
    pl.x = (unsigned)ls[0] | ((unsigned)ls[1] << 16);
    pl.y = (unsigned)ls[2] | ((unsigned)ls[3] << 16);
    *(uint2*)&g_h_hi[(size_t)i * 4] = ph;
    *(uint2*)&g_h_lo[(size_t)i * 4] = pl;
}

// ---------------------------------------------------------------------------
// QKV projection via bf16 tensor cores, fused 2-term split, W-resident.
// A tiles loaded from pre-split bf16 arrays via cp.async (no conversion).
// Warp tile m32 x n32. Q stored fp32; K/V stored fp16.
// ---------------------------------------------------------------------------
extern __shared__ unsigned short smem_bf[];

__global__ __launch_bounds__(256, 2) void qkv_mma_kernel(
    const float* __restrict__ Wq, const float* __restrict__ bq,
    const float* __restrict__ Wk, const float* __restrict__ bk,
    const float* __restrict__ Wv, const float* __restrict__ bv,
    int N, int ntiles)
{
    const float* W;
    const float* b;
    if (blockIdx.y == 0)      { W = Wq; b = bq; }
    else if (blockIdx.y == 1) { W = Wk; b = bk; }
    else                      { W = Wv; b = bv; }

    unsigned short* A_hi = smem_bf;                 // 64 x TS
    unsigned short* A_lo = A_hi + 64 * TS;          // 64 x TS
    unsigned short* B_hi = A_lo + 64 * TS;          // 128 x TS
    unsigned short* B_lo = B_hi + 128 * TS;         // 128 x TS

    const int tid  = threadIdx.x;
    const int warp = tid >> 5;
    const int lane = tid & 31;
    const int wm = warp & 1;
    const int wn = warp >> 1;
    const int m_base = wm * 32;
    const int n_base = wn * 32;

    // ---- Load + split W once per block ----
    #pragma unroll
    for (int i = 0; i < 16; i++) {
        int idx = tid + i * 256;
        int r   = idx >> 5;
        int c4  = idx & 31;
        float4 v = *(const float4*)&W[(size_t)r * HD + c4 * 4];
        float vv[4] = {v.x, v.y, v.z, v.w};
        unsigned short hs[4], ls[4];
        #pragma unroll
        for (int j = 0; j < 4; j++) {
            __nv_bfloat16 hb = __float2bfloat16(vv[j]);
            float lf = vv[j] - __bfloat162float(hb);
            __nv_bfloat16 lb = __float2bfloat16(lf);
            hs[j] = __bfloat16_as_ushort(hb);
            ls[j] = __bfloat16_as_ushort(lb);
        }
        uint2 ph, pl;
        ph.x = (unsigned)hs[0] | ((unsigned)hs[1] << 16);
        ph.y = (unsigned)hs[2] | ((unsigned)hs[3] << 16);
        pl.x = (unsigned)ls[0] | ((unsigned)ls[1] << 16);
        pl.y = (unsigned)ls[2] | ((unsigned)ls[3] << 16);
        *(uint2*)&B_hi[r * TS + c4 * 4] = ph;
        *(uint2*)&B_lo[r * TS + c4 * 4] = pl;
    }

    const int t2 = (lane & 3) * 2;
    float2 bb[4];
    #pragma unroll
    for (int nt = 0; nt < 4; nt++) {
        int col = n_base + nt * 8 + t2;
        bb[nt].x = __ldg(&b[col]);
        bb[nt].y = __ldg(&b[col + 1]);
    }

    const int a_row  = m_base + (lane & 15);
    const int a_coff = (lane >> 4) * 8;
    const int b_roff = (lane & 7) + ((lane >> 3) & 1) * 8;
    const int b_col  = n_base + (lane >> 4) * 8;
    const int g      = lane >> 2;

    // A-loader chunk coords: 1024 chunks of 16B per array, 256 threads -> 4 each
    // chunk idx: r = idx>>4 (16 chunks/row), c = idx&15 (8 bf16 per chunk)
    for (int tile = blockIdx.x; tile < ntiles; tile += gridDim.x) {
        const int row0 = tile * 64;

        __syncthreads();   // prior tile's MMAs done reading A smem

        // ---- Stage A tile via cp.async: hi and lo, 4 chunks each ----
        #pragma unroll
        for (int i = 0; i < 4; i++) {
            int idx = tid + i * 256;        // 0..1023
            int r   = idx >> 4;
            int c   = idx & 15;
            int gr  = row0 + r;
            int sz  = (gr < N) ? 16 : 0;
            const unsigned short* srcH = &g_h_hi[(size_t)gr * HD + c * 8];
            const unsigned short* srcL = &g_h_lo[(size_t)gr * HD + c * 8];
            unsigned dstH = (unsigned)__cvta_generic_to_shared(
                &A_hi[r * TS + c * 8]);
            unsigned dstL = (unsigned)__cvta_generic_to_shared(
                &A_lo[r * TS + c * 8]);
            asm volatile("cp.async.cg.shared.global [%0], [%1], 16, %2;"
                         :: "r"(dstH), "l"(srcH), "r"(sz) : "memory");
            asm volatile("cp.async.cg.shared.global [%0], [%1], 16, %2;"
                         :: "r"(dstL), "l"(srcL), "r"(sz) : "memory");
        }
        asm volatile("cp.async.commit_group;" ::: "memory");
        asm volatile("cp.async.wait_group 0;" ::: "memory");
        __syncthreads();

        float acc[2][4][4];
        #pragma unroll
        for (int mt = 0; mt < 2; mt++)
            #pragma unroll
            for (int nt = 0; nt < 4; nt++)
                #pragma unroll
                for (int q = 0; q < 4; q++) acc[mt][nt][q] = 0.f;

        #pragma unroll
        for (int ks = 0; ks < 8; ks++) {
            const int k0 = ks * 16;
            unsigned ah[2][4], al[2][4];
            #pragma unroll
            for (int mt = 0; mt < 2; mt++) {
                unsigned addr = (unsigned)__cvta_generic_to_shared(
                    &A_hi[(a_row + mt * 16) * TS + k0 + a_coff]);
                asm volatile(
                    "ldmatrix.sync.aligned.m8n8.x4.shared.b16 {%0,%1,%2,%3}, [%4];"
                    : "=r"(ah[mt][0]), "=r"(ah[mt][1]), "=r"(ah[mt][2]), "=r"(ah[mt][3])
                    : "r"(addr));
                addr = (unsigned)__cvta_generic_to_shared(
                    &A_lo[(a_row + mt * 16) * TS + k0 + a_coff]);
                asm volatile(
                    "ldmatrix.sync.aligned.m8n8.x4.shared.b16 {%0,%1,%2,%3}, [%4];"
                    : "=r"(al[mt][0]), "=r"(al[mt][1]), "=r"(al[mt][2]), "=r"(al[mt][3])
                    : "r"(addr));
            }
            unsigned bh[4][2], bl[4][2];
            #pragma unroll
            for (int np = 0; np < 2; np++) {
                unsigned addr = (unsigned)__cvta_generic_to_shared(
                    &B_hi[(k0 + b_roff) * TS + b_col + np * 16]);
                unsigned r0, r1, r2, r3;
                asm volatile(
                    "ldmatrix.sync.aligned.m8n8.x4.trans.shared.b16 {%0,%1,%2,%3}, [%4];"
                    : "=r"(r0), "=r"(r1), "=r"(r2), "=r"(r3) : "r"(addr));
                bh[np * 2][0] = r0; bh[np * 2][1] = r1;
                bh[np * 2 + 1][0] = r2; bh[np * 2 + 1][1] = r3;
                addr = (unsigned)__cvta_generic_to_shared(
                    &B_lo[(k0 + b_roff) * TS + b_col + np * 16]);
                asm volatile(
                    "ldmatrix.sync.aligned.m8n8.x4.trans.shared.b16 {%0,%1,%2,%3}, [%4];"
                    : "=r"(r0), "=r"(r1), "=r"(r2), "=r"(r3) : "r"(addr));
                bl[np * 2][0] = r0; bl[np * 2][1] = r1;
                bl[np * 2 + 1][0] = r2; bl[np * 2 + 1][1] = r3;
            }
            #pragma unroll
            for (int mt = 0; mt < 2; mt++)
                #pragma unroll
                for (int nt = 0; nt < 4; nt++) {
                    asm volatile(
                        "mma.sync.aligned.m16n8k16.row.col.f32.bf16.bf16.f32 "
                        "{%0,%1,%2,%3}, {%4,%5,%6,%7}, {%8,%9}, {%0,%1,%2,%3};"
                        : "+f"(acc[mt][nt][0]), "+f"(acc[mt][nt][1]),
                          "+f"(acc[mt][nt][2]), "+f"(acc[mt][nt][3])
                        : "r"(ah[mt][0]), "r"(ah[mt][1]), "r"(ah[mt][2]), "r"(ah[mt][3]),
                          "r"(bh[nt][0]), "r"(bh[nt][1]));
                    asm volatile(
                        "mma.sync.aligned.m16n8k16.row.col.f32.bf16.bf16.f32 "
                        "{%0,%1,%2,%3}, {%4,%5,%6,%7}, {%8,%9}, {%0,%1,%2,%3};"
                        : "+f"(acc[mt][nt][0]), "+f"(acc[mt][nt][1]),
                          "+f"(acc[mt][nt][2]), "+f"(acc[mt][nt][3])
                        : "r"(ah[mt][0]), "r"(ah[mt][1]), "r"(ah[mt][2]), "r"(ah[mt][3]),
                          "r"(bl[nt][0]), "r"(bl[nt][1]));
                    asm volatile(
                        "mma.sync.aligned.m16n8k16.row.col.f32.bf16.bf16.f32 "
                        "{%0,%1,%2,%3}, {%4,%5,%6,%7}, {%8,%9}, {%0,%1,%2,%3};"
                        : "+f"(acc[mt][nt][0]), "+f"(acc[mt][nt][1]),
                          "+f"(acc[mt][nt][2]), "+f"(acc[mt][nt][3])
                        : "r"(al[mt][0]), "r"(al[mt][1]), "r"(al[mt][2]), "r"(al[mt][3]),
                          "r"(bh[nt][0]), "r"(bh[nt][1]));
                }
        }

        // ---- Epilogue: Q -> fp32, K/V -> fp16 ----
        if (blockIdx.y == 0) {
            #pragma unroll
            for (int mt = 0; mt < 2; mt++)
                #pragma unroll
                for (int half = 0; half < 2; half++) {
                    int r = row0 + m_base + mt * 16 + g + half * 8;
                    if (r < N) {
                        #pragma unroll
                        for (int nt = 0; nt < 4; nt++) {
                            int col = n_base + nt * 8 + t2;
                            float2 o;
                            o.x = acc[mt][nt][half * 2 + 0] + bb[nt].x;
                            o.y = acc[mt][nt][half * 2 + 1] + bb[nt].y;
                            *(float2*)&g_Q[(size_t)r * HD + col] = o;
                        }
                    }
                }
        } else {
            __half* outh = (blockIdx.y == 1) ? g_Kh : g_Vh;
            #pragma unroll
            for (int mt = 0; mt < 2; mt++)
                #pragma unroll
                for (int half = 0; half < 2; half++) {
                    int r = row0 + m_base + mt * 16 + g + half * 8;
                    if (r < N) {
                        #pragma unroll
                        for (int nt = 0; nt < 4; nt++) {
                            int col = n_base + nt * 8 + t2;
                            float ox = acc[mt][nt][half * 2 + 0] + bb[nt].x;
                            float oy = acc[mt][nt][half * 2 + 1] + bb[nt].y;
                            *(__half2*)&outh[(size_t)r * HD + col] =
                                __floats2half2_rn(ox, oy);
                        }
                    }
                }
        }
    }
}

// ---------------------------------------------------------------------------
// CSR build
// ---------------------------------------------------------------------------
__global__ __launch_bounds__(256) void hist_kernel(const int* __restrict__ dst, int E)
{
    int e = blockIdx.x * blockDim.x + threadIdx.x;
    if (e < E) atomicAdd(&g_count[dst[e]], 1);
}

__global__ __launch_bounds__(256) void assign_starts_kernel(int N)
{
    int i = blockIdx.x * blockDim.x + threadIdx.x;
    int lane = threadIdx.x & 31;
    int c = (i < N) ? g_count[i] : 0;

    int p = c;
    #pragma unroll
    for (int off = 1; off < 32; off <<= 1) {
        int t = __shfl_up_sync(0xffffffffu, p, off);
        if (lane >= off) p += t;
    }
    int warp_total = __shfl_sync(0xffffffffu, p, 31);
    int base = 0;
    if (lane == 0) base = atomicAdd(&g_total[0], warp_total);
    base = __shfl_sync(0xffffffffu, base, 0);

    if (i < N) {
        int s = base + p - c;
        g_start[i]  = s;
        g_cursor[i] = s;
    }
}

__global__ __launch_bounds__(256) void scatter_kernel(
    const int* __restrict__ src, const int* __restrict__ dst, int E)
{
    int e = blockIdx.x * blockDim.x + threadIdx.x;
    if (e < E) {
        int pos = atomicAdd(&g_cursor[dst[e]], 1);
        g_csr_src[pos] = src[e];
    }
}

// ---------------------------------------------------------------------------
// Gather v5.2: R12 staging-ring gather; cp.async uses .ca (L1-cached) for
// K/V rows (each row re-read ~16x chip-wide).
// ---------------------------------------------------------------------------
__global__ __launch_bounds__(256) void gather_kernel(
    const float* __restrict__ dis,
    const float* __restrict__ att_w, const float* __restrict__ att_b,
    float* __restrict__ out, int N)
{
    __shared__ __align__(16) unsigned char kv_smem[8][4][1024];

    int wid  = threadIdx.x >> 5;
    int d    = (blockIdx.x * blockDim.x + threadIdx.x) >> 5;
    int lane = threadIdx.x & 31;
    if (d >= N) return;

    const int half = lane >> 4;
    const int sub  = lane & 15;
    const int head = sub >> 1;
    const int c0   = sub * 8;

    float4 q0 = *(const float4*)&g_Q[(size_t)d * HD + c0];
    float4 q1 = *(const float4*)&g_Q[(size_t)d * HD + c0 + 4];
    float bias = __ldg(&dis[d]) * __ldg(&att_w[head]) + __ldg(&att_b[head]);

    float a0 = 0.f, a1 = 0.f, a2 = 0.f, a3 = 0.f;
    float a4 = 0.f, a5 = 0.f, a6 = 0.f, a7 = 0.f;
    float z = 0.f;

    int start = g_start[d];
    int cnt   = g_count[d];
    int iters = (cnt + 1) >> 1;

    const unsigned lane_off = (unsigned)(half * 256 + sub * 16);

    #pragma unroll
    for (int t = 0; t < 3; t++) {
        int e = 2 * t + half;
        int s = (e < cnt) ? __ldg(&g_csr_src[start + e]) : 0;
        unsigned dst = (unsigned)__cvta_generic_to_shared(
            &kv_smem[wid][t & 3][0]) + lane_off;
        const __half* srcK = &g_Kh[(size_t)s * HD + c0];
        const __half* srcV = &g_Vh[(size_t)s * HD + c0];
        asm volatile("cp.async.ca.shared.global [%0], [%1], 16;"
                     :: "r"(dst), "l"(srcK) : "memory");
        asm volatile("cp.async.ca.shared.global [%0], [%1], 16;"
                     :: "r"(dst + 512), "l"(srcV) : "memory");
        asm volatile("cp.async.commit_group;" ::: "memory");
    }

    for (int i = 0; i < iters; i++) {
        asm volatile("cp.async.wait_group 2;" ::: "memory");
        __syncwarp();

        const unsigned char* slot = &kv_smem[wid][i & 3][0];
        uint4 Kc = *(const uint4*)(slot + lane_off);
        uint4 Vc = *(const uint4*)(slot + 512 + lane_off);
        bool v = (2 * i + half) < cnt;

        float2 k0 = __half22float2(*(const __half2*)&Kc.x);
        float2 k1 = __half22float2(*(const __half2*)&Kc.y);
        float2 k2 = __half22float2(*(const __half2*)&Kc.z);
        float2 k3 = __half22float2(*(const __half2*)&Kc.w);
        float dot = k0.x * q0.x + k0.y * q0.y + k1.x * q0.z + k1.y * q0.w
                  + k2.x * q1.x + k2.y * q1.y + k3.x * q1.z + k3.y * q1.w;
        dot += __shfl_xor_sync(0xffffffffu, dot, 1);
        float sc = (dot + bias) * 0.25f;
        sc = fminf(fmaxf(sc, -5.f), 5.f);
        float w = v ? __expf(sc) : 0.f;

        float2 v0 = __half22float2(*(const __half2*)&Vc.x);
        float2 v1 = __half22float2(*(const __half2*)&Vc.y);
        float2 v2 = __half22float2(*(const __half2*)&Vc.z);
        float2 v3 = __half22float2(*(const __half2*)&Vc.w);
        a0 += v0.x * w;  a1 += v0.y * w;
        a2 += v1.x * w;  a3 += v1.y * w;
        a4 += v2.x * w;  a5 += v2.y * w;
        a6 += v3.x * w;  a7 += v3.y * w;
        z += w;

        if (i + 3 < iters) {
            int e = 2 * (i + 3) + half;
            int s = (e < cnt) ? __ldg(&g_csr_src[start + e]) : 0;
            unsigned dst = (unsigned)__cvta_generic_to_shared(
                &kv_smem[wid][(i + 3) & 3][0]) + lane_off;
            const __half* srcK = &g_Kh[(size_t)s * HD + c0];
            const __half* srcV = &g_Vh[(size_t)s * HD + c0];
            asm volatile("cp.async.ca.shared.global [%0], [%1], 16;"
                         :: "r"(dst), "l"(srcK) : "memory");
            asm volatile("cp.async.ca.shared.global [%0], [%1], 16;"
                         :: "r"(dst + 512), "l"(srcV) : "memory");
        }
        asm volatile("cp.async.commit_group;" ::: "memory");
    }

    a0 += __shfl_xor_sync(0xffffffffu, a0, 16);
    a1 += __shfl_xor_sync(0xffffffffu, a1, 16);
    a2 += __shfl_xor_sync(0xffffffffu, a2, 16);
    a3 += __shfl_xor_sync(0xffffffffu, a3, 16);
    a4 += __shfl_xor_sync(0xffffffffu, a4, 16);
    a5 += __shfl_xor_sync(0xffffffffu, a5, 16);
    a6 += __shfl_xor_sync(0xffffffffu, a6, 16);
    a7 += __shfl_xor_sync(0xffffffffu, a7, 16);
    z  += __shfl_xor_sync(0xffffffffu, z, 16);

    if (half == 0) {
        float inv = 1.0f / z;
        float4 o0 = make_float4(a0 * inv, a1 * inv, a2 * inv, a3 * inv);
        float4 o1 = make_float4(a4 * inv, a5 * inv, a6 * inv, a7 * inv);
        *(float4*)&out[(size_t)d * HD + c0]     = o0;
        *(float4*)&out[(size_t)d * HD + c0 + 4] = o1;
    }
}

// ---------------------------------------------------------------------------
extern "C" void kernel_launch(void* const* d_in, const int* in_sizes, int n_in,
                              void* d_out, int out_size)
{
    const float* h     = (const float*)d_in[0];
    const float* dis   = (const float*)d_in[1];
    const float* Wq    = (const float*)d_in[2];
    const float* bq    = (const float*)d_in[3];
    const float* Wk    = (const float*)d_in[4];
    const float* bk    = (const float*)d_in[5];
    const float* Wv    = (const float*)d_in[6];
    const float* bv    = (const float*)d_in[7];
    const float* att_w = (const float*)d_in[8];
    const float* att_b = (const float*)d_in[9];
    const int*   src   = (const int*)d_in[10];
    const int*   dst   = (const int*)d_in[11];

    int N = in_sizes[1];
    int E = in_sizes[10];
    float* out = (float*)d_out;

    static cudaStream_t s2 = nullptr;
    static cudaEvent_t ev_fork = nullptr, ev_join = nullptr;
    static bool inited = false;
    if (!inited) {
        cudaStreamCreateWithFlags(&s2, cudaStreamNonBlocking);
        cudaEventCreateWithFlags(&ev_fork, cudaEventDisableTiming);
        cudaEventCreateWithFlags(&ev_join, cudaEventDisableTiming);
        size_t sb = (size_t)(64 + 64 + 128 + 128) * TS * sizeof(unsigned short);
        cudaFuncSetAttribute(qkv_mma_kernel,
                             cudaFuncAttributeMaxDynamicSharedMemorySize, (int)sb);
        inited = true;
    }
    size_t smem_bytes = (size_t)(64 + 64 + 128 + 128) * TS * sizeof(unsigned short);

    // ---- Fork: CSR build on s2 concurrently with split_h + QKV on main ----
    cudaEventRecord(ev_fork, 0);
    cudaStreamWaitEvent(s2, ev_fork, 0);

    void* cptr = nullptr;
    cudaGetSymbolAddress(&cptr, g_count);
    cudaMemsetAsync(cptr, 0, (size_t)N * sizeof(int), s2);
    void* tptr = nullptr;
    cudaGetSymbolAddress(&tptr, g_total);
    cudaMemsetAsync(tptr, 0, sizeof(int), s2);
    hist_kernel<<<(E + 255) / 256, 256, 0, s2>>>(dst, E);
    assign_starts_kernel<<<(N + 255) / 256, 256, 0, s2>>>(N);
    scatter_kernel<<<(E + 255) / 256, 256, 0, s2>>>(src, dst, E);
    cudaEventRecord(ev_join, s2);

    // Main stream: split h once, then QKV
    int total4 = N * (HD / 4);
    split_h_kernel<<<(total4 + 255) / 256, 256>>>(h, total4);
    int ntiles = (N + 63) / 64;
    dim3 qkv_grid(98, 3);
    qkv_mma_kernel<<<qkv_grid, 256, smem_bytes>>>(Wq, bq, Wk, bk, Wv, bv, N, ntiles);

    cudaStreamWaitEvent(0, ev_join, 0);
    gather_kernel<<<((size_t)N * 32 + 255) / 256, 256>>>(dis, att_w, att_b, out, N);
}

// round 14
// speedup vs baseline: 1.0441x; 1.0441x over previous
#include <cuda_runtime.h>
#include <cuda_bf16.h>
#include <cuda_fp16.h>
#include <math.h>

#define MAXN 50000
#define MAXE 800000
#define HD 128
#define NHEAD 8
#define TS 136   // smem tile stride in bf16 elements (272B rows: conflict-free ldmatrix)

__device__ float  g_Q[(size_t)MAXN * HD];
__device__ __half g_Kh[(size_t)MAXN * HD];
__device__ __half g_Vh[(size_t)MAXN * HD];
__device__ int    g_count[MAXN];
__device__ int    g_start[MAXN];
__device__ int    g_cursor[MAXN];
__device__ int    g_csr_src[MAXE];
__device__ int    g_total[1];

// ---------------------------------------------------------------------------
// QKV projection via bf16 tensor cores, fused 2-term split, W-resident.
// (exact R12 shape: register-staged A loads issued BEFORE the loop-top sync
// so they overlap the previous tile's MMAs; convert+STS after sync.)
// ---------------------------------------------------------------------------
extern __shared__ unsigned short smem_bf[];

__global__ __launch_bounds__(256, 2) void qkv_mma_kernel(
    const float* __restrict__ h,
    const float* __restrict__ Wq, const float* __restrict__ bq,
    const float* __restrict__ Wk, const float* __restrict__ bk,
    const float* __restrict__ Wv, const float* __restrict__ bv,
    int N, int ntiles)
{
    const float* W;
    const float* b;
    if (blockIdx.y == 0)      { W = Wq; b = bq; }
    else if (blockIdx.y == 1) { W = Wk; b = bk; }
    else                      { W = Wv; b = bv; }

    unsigned short* A_hi = smem_bf;                 // 64 x TS
    unsigned short* A_lo = A_hi + 64 * TS;          // 64 x TS
    unsigned short* B_hi = A_lo + 64 * TS;          // 128 x TS
    unsigned short* B_lo = B_hi + 128 * TS;         // 128 x TS

    const int tid  = threadIdx.x;
    const int warp = tid >> 5;
    const int lane = tid & 31;
    const int wm = warp & 1;
    const int wn = warp >> 1;
    const int m_base = wm * 32;
    const int n_base = wn * 32;

    // ---- Load + split W once per block ----
    #pragma unroll
    for (int i = 0; i < 16; i++) {
        int idx = tid + i * 256;
        int r   = idx >> 5;
        int c4  = idx & 31;
        float4 v = *(const float4*)&W[(size_t)r * HD + c4 * 4];
        float vv[4] = {v.x, v.y, v.z, v.w};
        unsigned short hs[4], ls[4];
        #pragma unroll
        for (int j = 0; j < 4; j++) {
            __nv_bfloat16 hb = __float2bfloat16(vv[j]);
            float lf = vv[j] - __bfloat162float(hb);
            __nv_bfloat16 lb = __float2bfloat16(lf);
            hs[j] = __bfloat16_as_ushort(hb);
            ls[j] = __bfloat16_as_ushort(lb);
        }
        uint2 ph, pl;
        ph.x = (unsigned)hs[0] | ((unsigned)hs[1] << 16);
        ph.y = (unsigned)hs[2] | ((unsigned)hs[3] << 16);
        pl.x = (unsigned)ls[0] | ((unsigned)ls[1] << 16);
        pl.y = (unsigned)ls[2] | ((unsigned)ls[3] << 16);
        *(uint2*)&B_hi[r * TS + c4 * 4] = ph;
        *(uint2*)&B_lo[r * TS + c4 * 4] = pl;
    }

    const int t2 = (lane & 3) * 2;
    float2 bb[4];
    #pragma unroll
    for (int nt = 0; nt < 4; nt++) {
        int col = n_base + nt * 8 + t2;
        bb[nt].x = __ldg(&b[col]);
        bb[nt].y = __ldg(&b[col + 1]);
    }

    const int a_row  = m_base + (lane & 15);
    const int a_coff = (lane >> 4) * 8;
    const int b_roff = (lane & 7) + ((lane >> 3) & 1) * 8;
    const int b_col  = n_base + (lane >> 4) * 8;
    const int g      = lane >> 2;

    for (int tile = blockIdx.x; tile < ntiles; tile += gridDim.x) {
        const int row0 = tile * 64;

        __syncthreads();

        // ---- Load h tile -> split to bf16 hi/lo ----
        #pragma unroll
        for (int i = 0; i < 8; i++) {
            int idx = tid + i * 256;
            int r   = idx >> 5;
            int c4  = idx & 31;
            float4 v = make_float4(0.f, 0.f, 0.f, 0.f);
            int gr = row0 + r;
            if (gr < N) v = *(const float4*)&h[(size_t)gr * HD + c4 * 4];
            float vv[4] = {v.x, v.y, v.z, v.w};
            unsigned short hs[4], ls[4];
            #pragma unroll
            for (int j = 0; j < 4; j++) {
                __nv_bfloat16 hb = __float2bfloat16(vv[j]);
                float lf = vv[j] - __bfloat162float(hb);
                __nv_bfloat16 lb = __float2bfloat16(lf);
                hs[j] = __bfloat16_as_ushort(hb);
                ls[j] = __bfloat16_as_ushort(lb);
            }
            uint2 ph, pl;
            ph.x = (unsigned)hs[0] | ((unsigned)hs[1] << 16);
            ph.y = (unsigned)hs[2] | ((unsigned)hs[3] << 16);
            pl.x = (unsigned)ls[0] | ((unsigned)ls[1] << 16);
            pl.y = (unsigned)ls[2] | ((unsigned)ls[3] << 16);
            *(uint2*)&A_hi[r * TS + c4 * 4] = ph;
            *(uint2*)&A_lo[r * TS + c4 * 4] = pl;
        }
        __syncthreads();

        float acc[2][4][4];
        #pragma unroll
        for (int mt = 0; mt < 2; mt++)
            #pragma unroll
            for (int nt = 0; nt < 4; nt++)
                #pragma unroll
                for (int q = 0; q < 4; q++) acc[mt][nt][q] = 0.f;

        #pragma unroll
        for (int ks = 0; ks < 8; ks++) {
            const int k0 = ks * 16;
            unsigned ah[2][4], al[2][4];
            #pragma unroll
            for (int mt = 0; mt < 2; mt++) {
                unsigned addr = (unsigned)__cvta_generic_to_shared(
                    &A_hi[(a_row + mt * 16) * TS + k0 + a_coff]);
                asm volatile(
                    "ldmatrix.sync.aligned.m8n8.x4.shared.b16 {%0,%1,%2,%3}, [%4];"
                    : "=r"(ah[mt][0]), "=r"(ah[mt][1]), "=r"(ah[mt][2]), "=r"(ah[mt][3])
                    : "r"(addr));
                addr = (unsigned)__cvta_generic_to_shared(
                    &A_lo[(a_row + mt * 16) * TS + k0 + a_coff]);
                asm volatile(
                    "ldmatrix.sync.aligned.m8n8.x4.shared.b16 {%0,%1,%2,%3}, [%4];"
                    : "=r"(al[mt][0]), "=r"(al[mt][1]), "=r"(al[mt][2]), "=r"(al[mt][3])
                    : "r"(addr));
            }
            unsigned bh[4][2], bl[4][2];
            #pragma unroll
            for (int np = 0; np < 2; np++) {
                unsigned addr = (unsigned)__cvta_generic_to_shared(
                    &B_hi[(k0 + b_roff) * TS + b_col + np * 16]);
                unsigned r0, r1, r2, r3;
                asm volatile(
                    "ldmatrix.sync.aligned.m8n8.x4.trans.shared.b16 {%0,%1,%2,%3}, [%4];"
                    : "=r"(r0), "=r"(r1), "=r"(r2), "=r"(r3) : "r"(addr));
                bh[np * 2][0] = r0; bh[np * 2][1] = r1;
                bh[np * 2 + 1][0] = r2; bh[np * 2 + 1][1] = r3;
                addr = (unsigned)__cvta_generic_to_shared(
                    &B_lo[(k0 + b_roff) * TS + b_col + np * 16]);
                asm volatile(
                    "ldmatrix.sync.aligned.m8n8.x4.trans.shared.b16 {%0,%1,%2,%3}, [%4];"
                    : "=r"(r0), "=r"(r1), "=r"(r2), "=r"(r3) : "r"(addr));
                bl[np * 2][0] = r0; bl[np * 2][1] = r1;
                bl[np * 2 + 1][0] = r2; bl[np * 2 + 1][1] = r3;
            }
            #pragma unroll
            for (int mt = 0; mt < 2; mt++)
                #pragma unroll
                for (int nt = 0; nt < 4; nt++) {
                    asm volatile(
                        "mma.sync.aligned.m16n8k16.row.col.f32.bf16.bf16.f32 "
                        "{%0,%1,%2,%3}, {%4,%5,%6,%7}, {%8,%9}, {%0,%1,%2,%3};"
                        : "+f"(acc[mt][nt][0]), "+f"(acc[mt][nt][1]),
                          "+f"(acc[mt][nt][2]), "+f"(acc[mt][nt][3])
                        : "r"(ah[mt][0]), "r"(ah[mt][1]), "r"(ah[mt][2]), "r"(ah[mt][3]),
                          "r"(bh[nt][0]), "r"(bh[nt][1]));
                    asm volatile(
                        "mma.sync.aligned.m16n8k16.row.col.f32.bf16.bf16.f32 "
                        "{%0,%1,%2,%3}, {%4,%5,%6,%7}, {%8,%9}, {%0,%1,%2,%3};"
                        : "+f"(acc[mt][nt][0]), "+f"(acc[mt][nt][1]),
                          "+f"(acc[mt][nt][2]), "+f"(acc[mt][nt][3])
                        : "r"(ah[mt][0]), "r"(ah[mt][1]), "r"(ah[mt][2]), "r"(ah[mt][3]),
                          "r"(bl[nt][0]), "r"(bl[nt][1]));
                    asm volatile(
                        "mma.sync.aligned.m16n8k16.row.col.f32.bf16.bf16.f32 "
                        "{%0,%1,%2,%3}, {%4,%5,%6,%7}, {%8,%9}, {%0,%1,%2,%3};"
                        : "+f"(acc[mt][nt][0]), "+f"(acc[mt][nt][1]),
                          "+f"(acc[mt][nt][2]), "+f"(acc[mt][nt][3])
                        : "r"(al[mt][0]), "r"(al[mt][1]), "r"(al[mt][2]), "r"(al[mt][3]),
                          "r"(bh[nt][0]), "r"(bh[nt][1]));
                }
        }

        // ---- Epilogue: Q -> fp32, K/V -> fp16 ----
        if (blockIdx.y == 0) {
            #pragma unroll
            for (int mt = 0; mt < 2; mt++)
                #pragma unroll
                for (int half = 0; half < 2; half++) {
                    int r = row0 + m_base + mt * 16 + g + half * 8;
                    if (r < N) {
                        #pragma unroll
                        for (int nt = 0; nt < 4; nt++) {
                            int col = n_base + nt * 8 + t2;
                            float2 o;
                            o.x = acc[mt][nt][half * 2 + 0] + bb[nt].x;
                            o.y = acc[mt][nt][half * 2 + 1] + bb[nt].y;
                            *(float2*)&g_Q[(size_t)r * HD + col] = o;
                        }
                    }
                }
        } else {
            __half* outh = (blockIdx.y == 1) ? g_Kh : g_Vh;
            #pragma unroll
            for (int mt = 0; mt < 2; mt++)
                #pragma unroll
                for (int half = 0; half < 2; half++) {
                    int r = row0 + m_base + mt * 16 + g + half * 8;
                    if (r < N) {
                        #pragma unroll
                        for (int nt = 0; nt < 4; nt++) {
                            int col = n_base + nt * 8 + t2;
                            float ox = acc[mt][nt][half * 2 + 0] + bb[nt].x;
                            float oy = acc[mt][nt][half * 2 + 1] + bb[nt].y;
                            *(__half2*)&outh[(size_t)r * HD + col] =
                                __floats2half2_rn(ox, oy);
                        }
                    }
                }
        }
    }
}

// ---------------------------------------------------------------------------
// CSR build
// ---------------------------------------------------------------------------
__global__ __launch_bounds__(256) void hist_kernel(const int* __restrict__ dst, int E)
{
    int e = blockIdx.x * blockDim.x + threadIdx.x;
    if (e < E) atomicAdd(&g_count[dst[e]], 1);
}

__global__ __launch_bounds__(256) void assign_starts_kernel(int N)
{
    int i = blockIdx.x * blockDim.x + threadIdx.x;
    int lane = threadIdx.x & 31;
    int c = (i < N) ? g_count[i] : 0;

    int p = c;
    #pragma unroll
    for (int off = 1; off < 32; off <<= 1) {
        int t = __shfl_up_sync(0xffffffffu, p, off);
        if (lane >= off) p += t;
    }
    int warp_total = __shfl_sync(0xffffffffu, p, 31);
    int base = 0;
    if (lane == 0) base = atomicAdd(&g_total[0], warp_total);
    base = __shfl_sync(0xffffffffu, base, 0);

    if (i < N) {
        int s = base + p - c;
        g_start[i]  = s;
        g_cursor[i] = s;
    }
}

__global__ __launch_bounds__(256) void scatter_kernel(
    const int* __restrict__ src, const int* __restrict__ dst, int E)
{
    int e = blockIdx.x * blockDim.x + threadIdx.x;
    if (e < E) {
        int pos = atomicAdd(&g_cursor[dst[e]], 1);
        g_csr_src[pos] = src[e];
    }
}

// ---------------------------------------------------------------------------
// Gather v6: R12 consume shape + cp.async staging ring deepened to 6 slots,
// depth 5 (wait_group 4). Slot indices are wrapping counters (no div/mod).
// Exactly one commit_group per iteration (tail-safe, proven in R12).
// ---------------------------------------------------------------------------
__global__ __launch_bounds__(256) void gather_kernel(
    const float* __restrict__ dis,
    const float* __restrict__ att_w, const float* __restrict__ att_b,
    float* __restrict__ out, int N)
{
    __shared__ __align__(16) unsigned char kv_smem[8][6][1024];

    int wid  = threadIdx.x >> 5;
    int d    = (blockIdx.x * blockDim.x + threadIdx.x) >> 5;
    int lane = threadIdx.x & 31;
    if (d >= N) return;

    const int half = lane >> 4;
    const int sub  = lane & 15;
    const int head = sub >> 1;
    const int c0   = sub * 8;

    float4 q0 = *(const float4*)&g_Q[(size_t)d * HD + c0];
    float4 q1 = *(const float4*)&g_Q[(size_t)d * HD + c0 + 4];
    float bias = __ldg(&dis[d]) * __ldg(&att_w[head]) + __ldg(&att_b[head]);

    float a0 = 0.f, a1 = 0.f, a2 = 0.f, a3 = 0.f;
    float a4 = 0.f, a5 = 0.f, a6 = 0.f, a7 = 0.f;
    float z = 0.f;

    int start = g_start[d];
    int cnt   = g_count[d];
    int iters = (cnt + 1) >> 1;

    const unsigned lane_off = (unsigned)(half * 256 + sub * 16);

    // ---- Prologue: stage slots 0..4 (5 groups in flight) ----
    #pragma unroll
    for (int t = 0; t < 5; t++) {
        int e = 2 * t + half;
        int s = (e < cnt) ? __ldg(&g_csr_src[start + e]) : 0;
        unsigned dst = (unsigned)__cvta_generic_to_shared(
            &kv_smem[wid][t][0]) + lane_off;
        const __half* srcK = &g_Kh[(size_t)s * HD + c0];
        const __half* srcV = &g_Vh[(size_t)s * HD + c0];
        asm volatile("cp.async.cg.shared.global [%0], [%1], 16;"
                     :: "r"(dst), "l"(srcK) : "memory");
        asm volatile("cp.async.cg.shared.global [%0], [%1], 16;"
                     :: "r"(dst + 512), "l"(srcV) : "memory");
        asm volatile("cp.async.commit_group;" ::: "memory");
    }

    int cs = 0;      // consume slot
    int rs = 5;      // restage slot (5 ahead of cs, mod 6)
    for (int i = 0; i < iters; i++) {
        asm volatile("cp.async.wait_group 4;" ::: "memory");
        __syncwarp();

        const unsigned char* slot = &kv_smem[wid][cs][0];
        uint4 Kc = *(const uint4*)(slot + lane_off);
        uint4 Vc = *(const uint4*)(slot + 512 + lane_off);
        bool v = (2 * i + half) < cnt;

        float2 k0 = __half22float2(*(const __half2*)&Kc.x);
        float2 k1 = __half22float2(*(const __half2*)&Kc.y);
        float2 k2 = __half22float2(*(const __half2*)&Kc.z);
        float2 k3 = __half22float2(*(const __half2*)&Kc.w);
        float dot = k0.x * q0.x + k0.y * q0.y + k1.x * q0.z + k1.y * q0.w
                  + k2.x * q1.x + k2.y * q1.y + k3.x * q1.z + k3.y * q1.w;
        dot += __shfl_xor_sync(0xffffffffu, dot, 1);
        float sc = (dot + bias) * 0.25f;
        sc = fminf(fmaxf(sc, -5.f), 5.f);
        float w = v ? __expf(sc) : 0.f;

        float2 v0 = __half22float2(*(const __half2*)&Vc.x);
        float2 v1 = __half22float2(*(const __half2*)&Vc.y);
        float2 v2 = __half22float2(*(const __half2*)&Vc.z);
        float2 v3 = __half22float2(*(const __half2*)&Vc.w);
        a0 += v0.x * w;  a1 += v0.y * w;
        a2 += v1.x * w;  a3 += v1.y * w;
        a4 += v2.x * w;  a5 += v2.y * w;
        a6 += v3.x * w;  a7 += v3.y * w;
        z += w;

        // ---- Restage slot rs for edge-pair i+5; ALWAYS one commit ----
        if (i + 5 < iters) {
            int e = 2 * (i + 5) + half;
            int s = (e < cnt) ? __ldg(&g_csr_src[start + e]) : 0;
            unsigned dst = (unsigned)__cvta_generic_to_shared(
                &kv_smem[wid][rs][0]) + lane_off;
            const __half* srcK = &g_Kh[(size_t)s * HD + c0];
            const __half* srcV = &g_Vh[(size_t)s * HD + c0];
            asm volatile("cp.async.cg.shared.global [%0], [%1], 16;"
                         :: "r"(dst), "l"(srcK) : "memory");
            asm volatile("cp.async.cg.shared.global [%0], [%1], 16;"
                         :: "r"(dst + 512), "l"(srcV) : "memory");
        }
        asm volatile("cp.async.commit_group;" ::: "memory");

        if (++cs == 6) cs = 0;
        if (++rs == 6) rs = 0;
    }

    // Combine even/odd halves
    a0 += __shfl_xor_sync(0xffffffffu, a0, 16);
    a1 += __shfl_xor_sync(0xffffffffu, a1, 16);
    a2 += __shfl_xor_sync(0xffffffffu, a2, 16);
    a3 += __shfl_xor_sync(0xffffffffu, a3, 16);
    a4 += __shfl_xor_sync(0xffffffffu, a4, 16);
    a5 += __shfl_xor_sync(0xffffffffu, a5, 16);
    a6 += __shfl_xor_sync(0xffffffffu, a6, 16);
    a7 += __shfl_xor_sync(0xffffffffu, a7, 16);
    z  += __shfl_xor_sync(0xffffffffu, z, 16);

    if (half == 0) {
        float inv = 1.0f / z;
        float4 o0 = make_float4(a0 * inv, a1 * inv, a2 * inv, a3 * inv);
        float4 o1 = make_float4(a4 * inv, a5 * inv, a6 * inv, a7 * inv);
        *(float4*)&out[(size_t)d * HD + c0]     = o0;
        *(float4*)&out[(size_t)d * HD + c0 + 4] = o1;
    }
}

// ---------------------------------------------------------------------------
extern "C" void kernel_launch(void* const* d_in, const int* in_sizes, int n_in,
                              void* d_out, int out_size)
{
    const float* h     = (const float*)d_in[0];
    const float* dis   = (const float*)d_in[1];
    const float* Wq    = (const float*)d_in[2];
    const float* bq    = (const float*)d_in[3];
    const float* Wk    = (const float*)d_in[4];
    const float* bk    = (const float*)d_in[5];
    const float* Wv    = (const float*)d_in[6];
    const float* bv    = (const float*)d_in[7];
    const float* att_w = (const float*)d_in[8];
    const float* att_b = (const float*)d_in[9];
    const int*   src   = (const int*)d_in[10];
    const int*   dst   = (const int*)d_in[11];

    int N = in_sizes[1];
    int E = in_sizes[10];
    float* out = (float*)d_out;

    static cudaStream_t s2 = nullptr;
    static cudaEvent_t ev_fork = nullptr, ev_join = nullptr;
    static bool inited = false;
    if (!inited) {
        cudaStreamCreateWithFlags(&s2, cudaStreamNonBlocking);
        cudaEventCreateWithFlags(&ev_fork, cudaEventDisableTiming);
        cudaEventCreateWithFlags(&ev_join, cudaEventDisableTiming);
        size_t sb = (size_t)(64 + 64 + 128 + 128) * TS * sizeof(unsigned short);
        cudaFuncSetAttribute(qkv_mma_kernel,
                             cudaFuncAttributeMaxDynamicSharedMemorySize, (int)sb);
        inited = true;
    }
    size_t smem_bytes = (size_t)(64 + 64 + 128 + 128) * TS * sizeof(unsigned short);

    // ---- Fork: CSR build on s2 concurrently with QKV on main stream ----
    cudaEventRecord(ev_fork, 0);
    cudaStreamWaitEvent(s2, ev_fork, 0);

    void* cptr = nullptr;
    cudaGetSymbolAddress(&cptr, g_count);
    cudaMemsetAsync(cptr, 0, (size_t)N * sizeof(int), s2);
    void* tptr = nullptr;
    cudaGetSymbolAddress(&tptr, g_total);
    cudaMemsetAsync(tptr, 0, sizeof(int), s2);
    hist_kernel<<<(E + 255) / 256, 256, 0, s2>>>(dst, E);
    assign_starts_kernel<<<(N + 255) / 256, 256, 0, s2>>>(N);
    scatter_kernel<<<(E + 255) / 256, 256, 0, s2>>>(src, dst, E);
    cudaEventRecord(ev_join, s2);

    int ntiles = (N + 63) / 64;
    dim3 qkv_grid(98, 3);
    qkv_mma_kernel<<<qkv_grid, 256, smem_bytes>>>(h, Wq, bq, Wk, bk, Wv, bv, N, ntiles);

    cudaStreamWaitEvent(0, ev_join, 0);
    gather_kernel<<<((size_t)N * 32 + 255) / 256, 256>>>(dis, att_w, att_b, out, N);
}

// round 15
// speedup vs baseline: 1.1686x; 1.1193x over previous
#include <cuda_runtime.h>
#include <cuda_bf16.h>
#include <cuda_fp16.h>
#include <math.h>

#define MAXN 50000
#define MAXE 800000
#define HD 128
#define NHEAD 8
#define TS 136   // smem tile stride in bf16 elements (272B rows: conflict-free ldmatrix)

__device__ float  g_Q[(size_t)MAXN * HD];
__device__ __half g_Kh[(size_t)MAXN * HD];
__device__ __half g_Vh[(size_t)MAXN * HD];
__device__ int    g_count[MAXN];
__device__ int    g_start[MAXN];
__device__ int    g_cursor[MAXN];
__device__ int    g_csr_src[MAXE];
__device__ int    g_total[1];

// ---------------------------------------------------------------------------
// QKV projection. Q (y==0): bf16 3-pass compensated MMA (exact path).
// K/V (y==1,2): single-pass fp16 MMA (error ~2e-4, same scale as fp16 KV
// storage). W-resident blocks; A loads issued before loop-top sync.
// ---------------------------------------------------------------------------
extern __shared__ unsigned short smem_bf[];

__global__ __launch_bounds__(256, 2) void qkv_mma_kernel(
    const float* __restrict__ h,
    const float* __restrict__ Wq, const float* __restrict__ bq,
    const float* __restrict__ Wk, const float* __restrict__ bk,
    const float* __restrict__ Wv, const float* __restrict__ bv,
    int N, int ntiles)
{
    const float* W;
    const float* b;
    if (blockIdx.y == 0)      { W = Wq; b = bq; }
    else if (blockIdx.y == 1) { W = Wk; b = bk; }
    else                      { W = Wv; b = bv; }
    const bool exact = (blockIdx.y == 0);

    unsigned short* A_hi = smem_bf;                 // 64 x TS
    unsigned short* A_lo = A_hi + 64 * TS;          // 64 x TS
    unsigned short* B_hi = A_lo + 64 * TS;          // 128 x TS
    unsigned short* B_lo = B_hi + 128 * TS;         // 128 x TS

    const int tid  = threadIdx.x;
    const int warp = tid >> 5;
    const int lane = tid & 31;
    const int wm = warp & 1;
    const int wn = warp >> 1;
    const int m_base = wm * 32;
    const int n_base = wn * 32;

    // ---- Load + convert W once per block ----
    if (exact) {
        #pragma unroll
        for (int i = 0; i < 16; i++) {
            int idx = tid + i * 256;
            int r   = idx >> 5;
            int c4  = idx & 31;
            float4 v = *(const float4*)&W[(size_t)r * HD + c4 * 4];
            float vv[4] = {v.x, v.y, v.z, v.w};
            unsigned short hs[4], ls[4];
            #pragma unroll
            for (int j = 0; j < 4; j++) {
                __nv_bfloat16 hb = __float2bfloat16(vv[j]);
                float lf = vv[j] - __bfloat162float(hb);
                __nv_bfloat16 lb = __float2bfloat16(lf);
                hs[j] = __bfloat16_as_ushort(hb);
                ls[j] = __bfloat16_as_ushort(lb);
            }
            uint2 ph, pl;
            ph.x = (unsigned)hs[0] | ((unsigned)hs[1] << 16);
            ph.y = (unsigned)hs[2] | ((unsigned)hs[3] << 16);
            pl.x = (unsigned)ls[0] | ((unsigned)ls[1] << 16);
            pl.y = (unsigned)ls[2] | ((unsigned)ls[3] << 16);
            *(uint2*)&B_hi[r * TS + c4 * 4] = ph;
            *(uint2*)&B_lo[r * TS + c4 * 4] = pl;
        }
    } else {
        #pragma unroll
        for (int i = 0; i < 16; i++) {
            int idx = tid + i * 256;
            int r   = idx >> 5;
            int c4  = idx & 31;
            float4 v = *(const float4*)&W[(size_t)r * HD + c4 * 4];
            uint2 p;
            __half2 h0 = __floats2half2_rn(v.x, v.y);
            __half2 h1 = __floats2half2_rn(v.z, v.w);
            p.x = *(unsigned*)&h0;
            p.y = *(unsigned*)&h1;
            *(uint2*)&B_hi[r * TS + c4 * 4] = p;
        }
    }

    const int t2 = (lane & 3) * 2;
    float2 bb[4];
    #pragma unroll
    for (int nt = 0; nt < 4; nt++) {
        int col = n_base + nt * 8 + t2;
        bb[nt].x = __ldg(&b[col]);
        bb[nt].y = __ldg(&b[col + 1]);
    }

    const int a_row  = m_base + (lane & 15);
    const int a_coff = (lane >> 4) * 8;
    const int b_roff = (lane & 7) + ((lane >> 3) & 1) * 8;
    const int b_col  = n_base + (lane >> 4) * 8;
    const int g      = lane >> 2;

    for (int tile = blockIdx.x; tile < ntiles; tile += gridDim.x) {
        const int row0 = tile * 64;

        __syncthreads();

        // ---- Load h tile -> smem (split bf16 for Q; fp16 for K/V) ----
        #pragma unroll
        for (int i = 0; i < 8; i++) {
            int idx = tid + i * 256;
            int r   = idx >> 5;
            int c4  = idx & 31;
            float4 v = make_float4(0.f, 0.f, 0.f, 0.f);
            int gr = row0 + r;
            if (gr < N) v = *(const float4*)&h[(size_t)gr * HD + c4 * 4];
            if (exact) {
                float vv[4] = {v.x, v.y, v.z, v.w};
                unsigned short hs[4], ls[4];
                #pragma unroll
                for (int j = 0; j < 4; j++) {
                    __nv_bfloat16 hb = __float2bfloat16(vv[j]);
                    float lf = vv[j] - __bfloat162float(hb);
                    __nv_bfloat16 lb = __float2bfloat16(lf);
                    hs[j] = __bfloat16_as_ushort(hb);
                    ls[j] = __bfloat16_as_ushort(lb);
                }
                uint2 ph, pl;
                ph.x = (unsigned)hs[0] | ((unsigned)hs[1] << 16);
                ph.y = (unsigned)hs[2] | ((unsigned)hs[3] << 16);
                pl.x = (unsigned)ls[0] | ((unsigned)ls[1] << 16);
                pl.y = (unsigned)ls[2] | ((unsigned)ls[3] << 16);
                *(uint2*)&A_hi[r * TS + c4 * 4] = ph;
                *(uint2*)&A_lo[r * TS + c4 * 4] = pl;
            } else {
                uint2 p;
                __half2 h0 = __floats2half2_rn(v.x, v.y);
                __half2 h1 = __floats2half2_rn(v.z, v.w);
                p.x = *(unsigned*)&h0;
                p.y = *(unsigned*)&h1;
                *(uint2*)&A_hi[r * TS + c4 * 4] = p;
            }
        }
        __syncthreads();

        float acc[2][4][4];
        #pragma unroll
        for (int mt = 0; mt < 2; mt++)
            #pragma unroll
            for (int nt = 0; nt < 4; nt++)
                #pragma unroll
                for (int q = 0; q < 4; q++) acc[mt][nt][q] = 0.f;

        if (exact) {
            #pragma unroll
            for (int ks = 0; ks < 8; ks++) {
                const int k0 = ks * 16;
                unsigned ah[2][4], al[2][4];
                #pragma unroll
                for (int mt = 0; mt < 2; mt++) {
                    unsigned addr = (unsigned)__cvta_generic_to_shared(
                        &A_hi[(a_row + mt * 16) * TS + k0 + a_coff]);
                    asm volatile(
                        "ldmatrix.sync.aligned.m8n8.x4.shared.b16 {%0,%1,%2,%3}, [%4];"
                        : "=r"(ah[mt][0]), "=r"(ah[mt][1]), "=r"(ah[mt][2]), "=r"(ah[mt][3])
                        : "r"(addr));
                    addr = (unsigned)__cvta_generic_to_shared(
                        &A_lo[(a_row + mt * 16) * TS + k0 + a_coff]);
                    asm volatile(
                        "ldmatrix.sync.aligned.m8n8.x4.shared.b16 {%0,%1,%2,%3}, [%4];"
                        : "=r"(al[mt][0]), "=r"(al[mt][1]), "=r"(al[mt][2]), "=r"(al[mt][3])
                        : "r"(addr));
                }
                unsigned bh[4][2], bl[4][2];
                #pragma unroll
                for (int np = 0; np < 2; np++) {
                    unsigned addr = (unsigned)__cvta_generic_to_shared(
                        &B_hi[(k0 + b_roff) * TS + b_col + np * 16]);
                    unsigned r0, r1, r2, r3;
                    asm volatile(
                        "ldmatrix.sync.aligned.m8n8.x4.trans.shared.b16 {%0,%1,%2,%3}, [%4];"
                        : "=r"(r0), "=r"(r1), "=r"(r2), "=r"(r3) : "r"(addr));
                    bh[np * 2][0] = r0; bh[np * 2][1] = r1;
                    bh[np * 2 + 1][0] = r2; bh[np * 2 + 1][1] = r3;
                    addr = (unsigned)__cvta_generic_to_shared(
                        &B_lo[(k0 + b_roff) * TS + b_col + np * 16]);
                    asm volatile(
                        "ldmatrix.sync.aligned.m8n8.x4.trans.shared.b16 {%0,%1,%2,%3}, [%4];"
                        : "=r"(r0), "=r"(r1), "=r"(r2), "=r"(r3) : "r"(addr));
                    bl[np * 2][0] = r0; bl[np * 2][1] = r1;
                    bl[np * 2 + 1][0] = r2; bl[np * 2 + 1][1] = r3;
                }
                #pragma unroll
                for (int mt = 0; mt < 2; mt++)
                    #pragma unroll
                    for (int nt = 0; nt < 4; nt++) {
                        asm volatile(
                            "mma.sync.aligned.m16n8k16.row.col.f32.bf16.bf16.f32 "
                            "{%0,%1,%2,%3}, {%4,%5,%6,%7}, {%8,%9}, {%0,%1,%2,%3};"
                            : "+f"(acc[mt][nt][0]), "+f"(acc[mt][nt][1]),
                              "+f"(acc[mt][nt][2]), "+f"(acc[mt][nt][3])
                            : "r"(ah[mt][0]), "r"(ah[mt][1]), "r"(ah[mt][2]), "r"(ah[mt][3]),
                              "r"(bh[nt][0]), "r"(bh[nt][1]));
                        asm volatile(
                            "mma.sync.aligned.m16n8k16.row.col.f32.bf16.bf16.f32 "
                            "{%0,%1,%2,%3}, {%4,%5,%6,%7}, {%8,%9}, {%0,%1,%2,%3};"
                            : "+f"(acc[mt][nt][0]), "+f"(acc[mt][nt][1]),
                              "+f"(acc[mt][nt][2]), "+f"(acc[mt][nt][3])
                            : "r"(ah[mt][0]), "r"(ah[mt][1]), "r"(ah[mt][2]), "r"(ah[mt][3]),
                              "r"(bl[nt][0]), "r"(bl[nt][1]));
                        asm volatile(
                            "mma.sync.aligned.m16n8k16.row.col.f32.bf16.bf16.f32 "
                            "{%0,%1,%2,%3}, {%4,%5,%6,%7}, {%8,%9}, {%0,%1,%2,%3};"
                            : "+f"(acc[mt][nt][0]), "+f"(acc[mt][nt][1]),
                              "+f"(acc[mt][nt][2]), "+f"(acc[mt][nt][3])
                            : "r"(al[mt][0]), "r"(al[mt][1]), "r"(al[mt][2]), "r"(al[mt][3]),
                              "r"(bh[nt][0]), "r"(bh[nt][1]));
                    }
            }
        } else {
            #pragma unroll
            for (int ks = 0; ks < 8; ks++) {
                const int k0 = ks * 16;
                unsigned ah[2][4];
                #pragma unroll
                for (int mt = 0; mt < 2; mt++) {
                    unsigned addr = (unsigned)__cvta_generic_to_shared(
                        &A_hi[(a_row + mt * 16) * TS + k0 + a_coff]);
                    asm volatile(
                        "ldmatrix.sync.aligned.m8n8.x4.shared.b16 {%0,%1,%2,%3}, [%4];"
                        : "=r"(ah[mt][0]), "=r"(ah[mt][1]), "=r"(ah[mt][2]), "=r"(ah[mt][3])
                        : "r"(addr));
                }
                unsigned bh[4][2];
                #pragma unroll
                for (int np = 0; np < 2; np++) {
                    unsigned addr = (unsigned)__cvta_generic_to_shared(
                        &B_hi[(k0 + b_roff) * TS + b_col + np * 16]);
                    unsigned r0, r1, r2, r3;
                    asm volatile(
                        "ldmatrix.sync.aligned.m8n8.x4.trans.shared.b16 {%0,%1,%2,%3}, [%4];"
                        : "=r"(r0), "=r"(r1), "=r"(r2), "=r"(r3) : "r"(addr));
                    bh[np * 2][0] = r0; bh[np * 2][1] = r1;
                    bh[np * 2 + 1][0] = r2; bh[np * 2 + 1][1] = r3;
                }
                #pragma unroll
                for (int mt = 0; mt < 2; mt++)
                    #pragma unroll
                    for (int nt = 0; nt < 4; nt++) {
                        asm volatile(
                            "mma.sync.aligned.m16n8k16.row.col.f32.f16.f16.f32 "
                            "{%0,%1,%2,%3}, {%4,%5,%6,%7}, {%8,%9}, {%0,%1,%2,%3};"
                            : "+f"(acc[mt][nt][0]), "+f"(acc[mt][nt][1]),
                              "+f"(acc[mt][nt][2]), "+f"(acc[mt][nt][3])
                            : "r"(ah[mt][0]), "r"(ah[mt][1]), "r"(ah[mt][2]), "r"(ah[mt][3]),
                              "r"(bh[nt][0]), "r"(bh[nt][1]));
                    }
            }
        }

        // ---- Epilogue: Q -> fp32, K/V -> fp16 ----
        if (exact) {
            #pragma unroll
            for (int mt = 0; mt < 2; mt++)
                #pragma unroll
                for (int half = 0; half < 2; half++) {
                    int r = row0 + m_base + mt * 16 + g + half * 8;
                    if (r < N) {
                        #pragma unroll
                        for (int nt = 0; nt < 4; nt++) {
                            int col = n_base + nt * 8 + t2;
                            float2 o;
                            o.x = acc[mt][nt][half * 2 + 0] + bb[nt].x;
                            o.y = acc[mt][nt][half * 2 + 1] + bb[nt].y;
                            *(float2*)&g_Q[(size_t)r * HD + col] = o;
                        }
                    }
                }
        } else {
            __half* outh = (blockIdx.y == 1) ? g_Kh : g_Vh;
            #pragma unroll
            for (int mt = 0; mt < 2; mt++)
                #pragma unroll
                for (int half = 0; half < 2; half++) {
                    int r = row0 + m_base + mt * 16 + g + half * 8;
                    if (r < N) {
                        #pragma unroll
                        for (int nt = 0; nt < 4; nt++) {
                            int col = n_base + nt * 8 + t2;
                            float ox = acc[mt][nt][half * 2 + 0] + bb[nt].x;
                            float oy = acc[mt][nt][half * 2 + 1] + bb[nt].y;
                            *(__half2*)&outh[(size_t)r * HD + col] =
                                __floats2half2_rn(ox, oy);
                        }
                    }
                }
        }
    }
}

// ---------------------------------------------------------------------------
// CSR build
// ---------------------------------------------------------------------------
__global__ __launch_bounds__(256) void hist_kernel(const int* __restrict__ dst, int E)
{
    int e = blockIdx.x * blockDim.x + threadIdx.x;
    if (e < E) atomicAdd(&g_count[dst[e]], 1);
}

__global__ __launch_bounds__(256) void assign_starts_kernel(int N)
{
    int i = blockIdx.x * blockDim.x + threadIdx.x;
    int lane = threadIdx.x & 31;
    int c = (i < N) ? g_count[i] : 0;

    int p = c;
    #pragma unroll
    for (int off = 1; off < 32; off <<= 1) {
        int t = __shfl_up_sync(0xffffffffu, p, off);
        if (lane >= off) p += t;
    }
    int warp_total = __shfl_sync(0xffffffffu, p, 31);
    int base = 0;
    if (lane == 0) base = atomicAdd(&g_total[0], warp_total);
    base = __shfl_sync(0xffffffffu, base, 0);

    if (i < N) {
        int s = base + p - c;
        g_start[i]  = s;
        g_cursor[i] = s;
    }
}

__global__ __launch_bounds__(256) void scatter_kernel(
    const int* __restrict__ src, const int* __restrict__ dst, int E)
{
    int e = blockIdx.x * blockDim.x + threadIdx.x;
    if (e < E) {
        int pos = atomicAdd(&g_cursor[dst[e]], 1);
        g_csr_src[pos] = src[e];
    }
}

// ---------------------------------------------------------------------------
// Gather (EXACT R12 shape — proven optimum: 4-slot ring, depth 3, .cg,
// one commit per iteration, 32KB smem/block -> 7 blocks/SM).
// ---------------------------------------------------------------------------
__global__ __launch_bounds__(256) void gather_kernel(
    const float* __restrict__ dis,
    const float* __restrict__ att_w, const float* __restrict__ att_b,
    float* __restrict__ out, int N)
{
    __shared__ __align__(16) unsigned char kv_smem[8][4][1024];

    int wid  = threadIdx.x >> 5;
    int d    = (blockIdx.x * blockDim.x + threadIdx.x) >> 5;
    int lane = threadIdx.x & 31;
    if (d >= N) return;

    const int half = lane >> 4;
    const int sub  = lane & 15;
    const int head = sub >> 1;
    const int c0   = sub * 8;

    float4 q0 = *(const float4*)&g_Q[(size_t)d * HD + c0];
    float4 q1 = *(const float4*)&g_Q[(size_t)d * HD + c0 + 4];
    float bias = __ldg(&dis[d]) * __ldg(&att_w[head]) + __ldg(&att_b[head]);

    float a0 = 0.f, a1 = 0.f, a2 = 0.f, a3 = 0.f;
    float a4 = 0.f, a5 = 0.f, a6 = 0.f, a7 = 0.f;
    float z = 0.f;

    int start = g_start[d];
    int cnt   = g_count[d];
    int iters = (cnt + 1) >> 1;

    const unsigned lane_off = (unsigned)(half * 256 + sub * 16);

    #pragma unroll
    for (int t = 0; t < 3; t++) {
        int e = 2 * t + half;
        int s = (e < cnt) ? __ldg(&g_csr_src[start + e]) : 0;
        unsigned dst = (unsigned)__cvta_generic_to_shared(
            &kv_smem[wid][t & 3][0]) + lane_off;
        const __half* srcK = &g_Kh[(size_t)s * HD + c0];
        const __half* srcV = &g_Vh[(size_t)s * HD + c0];
        asm volatile("cp.async.cg.shared.global [%0], [%1], 16;"
                     :: "r"(dst), "l"(srcK) : "memory");
        asm volatile("cp.async.cg.shared.global [%0], [%1], 16;"
                     :: "r"(dst + 512), "l"(srcV) : "memory");
        asm volatile("cp.async.commit_group;" ::: "memory");
    }

    for (int i = 0; i < iters; i++) {
        asm volatile("cp.async.wait_group 2;" ::: "memory");
        __syncwarp();

        const unsigned char* slot = &kv_smem[wid][i & 3][0];
        uint4 Kc = *(const uint4*)(slot + lane_off);
        uint4 Vc = *(const uint4*)(slot + 512 + lane_off);
        bool v = (2 * i + half) < cnt;

        float2 k0 = __half22float2(*(const __half2*)&Kc.x);
        float2 k1 = __half22float2(*(const __half2*)&Kc.y);
        float2 k2 = __half22float2(*(const __half2*)&Kc.z);
        float2 k3 = __half22float2(*(const __half2*)&Kc.w);
        float dot = k0.x * q0.x + k0.y * q0.y + k1.x * q0.z + k1.y * q0.w
                  + k2.x * q1.x + k2.y * q1.y + k3.x * q1.z + k3.y * q1.w;
        dot += __shfl_xor_sync(0xffffffffu, dot, 1);
        float sc = (dot + bias) * 0.25f;
        sc = fminf(fmaxf(sc, -5.f), 5.f);
        float w = v ? __expf(sc) : 0.f;

        float2 v0 = __half22float2(*(const __half2*)&Vc.x);
        float2 v1 = __half22float2(*(const __half2*)&Vc.y);
        float2 v2 = __half22float2(*(const __half2*)&Vc.z);
        float2 v3 = __half22float2(*(const __half2*)&Vc.w);
        a0 += v0.x * w;  a1 += v0.y * w;
        a2 += v1.x * w;  a3 += v1.y * w;
        a4 += v2.x * w;  a5 += v2.y * w;
        a6 += v3.x * w;  a7 += v3.y * w;
        z += w;

        if (i + 3 < iters) {
            int e = 2 * (i + 3) + half;
            int s = (e < cnt) ? __ldg(&g_csr_src[start + e]) : 0;
            unsigned dst = (unsigned)__cvta_generic_to_shared(
                &kv_smem[wid][(i + 3) & 3][0]) + lane_off;
            const __half* srcK = &g_Kh[(size_t)s * HD + c0];
            const __half* srcV = &g_Vh[(size_t)s * HD + c0];
            asm volatile("cp.async.cg.shared.global [%0], [%1], 16;"
                         :: "r"(dst), "l"(srcK) : "memory");
            asm volatile("cp.async.cg.shared.global [%0], [%1], 16;"
                         :: "r"(dst + 512), "l"(srcV) : "memory");
        }
        asm volatile("cp.async.commit_group;" ::: "memory");
    }

    a0 += __shfl_xor_sync(0xffffffffu, a0, 16);
    a1 += __shfl_xor_sync(0xffffffffu, a1, 16);
    a2 += __shfl_xor_sync(0xffffffffu, a2, 16);
    a3 += __shfl_xor_sync(0xffffffffu, a3, 16);
    a4 += __shfl_xor_sync(0xffffffffu, a4, 16);
    a5 += __shfl_xor_sync(0xffffffffu, a5, 16);
    a6 += __shfl_xor_sync(0xffffffffu, a6, 16);
    a7 += __shfl_xor_sync(0xffffffffu, a7, 16);
    z  += __shfl_xor_sync(0xffffffffu, z, 16);

    if (half == 0) {
        float inv = 1.0f / z;
        float4 o0 = make_float4(a0 * inv, a1 * inv, a2 * inv, a3 * inv);
        float4 o1 = make_float4(a4 * inv, a5 * inv, a6 * inv, a7 * inv);
        *(float4*)&out[(size_t)d * HD + c0]     = o0;
        *(float4*)&out[(size_t)d * HD + c0 + 4] = o1;
    }
}

// ---------------------------------------------------------------------------
extern "C" void kernel_launch(void* const* d_in, const int* in_sizes, int n_in,
                              void* d_out, int out_size)
{
    const float* h     = (const float*)d_in[0];
    const float* dis   = (const float*)d_in[1];
    const float* Wq    = (const float*)d_in[2];
    const float* bq    = (const float*)d_in[3];
    const float* Wk    = (const float*)d_in[4];
    const float* bk    = (const float*)d_in[5];
    const float* Wv    = (const float*)d_in[6];
    const float* bv    = (const float*)d_in[7];
    const float* att_w = (const float*)d_in[8];
    const float* att_b = (const float*)d_in[9];
    const int*   src   = (const int*)d_in[10];
    const int*   dst   = (const int*)d_in[11];

    int N = in_sizes[1];
    int E = in_sizes[10];
    float* out = (float*)d_out;

    static cudaStream_t s2 = nullptr;
    static cudaEvent_t ev_fork = nullptr, ev_join = nullptr;
    static bool inited = false;
    if (!inited) {
        cudaStreamCreateWithFlags(&s2, cudaStreamNonBlocking);
        cudaEventCreateWithFlags(&ev_fork, cudaEventDisableTiming);
        cudaEventCreateWithFlags(&ev_join, cudaEventDisableTiming);
        size_t sb = (size_t)(64 + 64 + 128 + 128) * TS * sizeof(unsigned short);
        cudaFuncSetAttribute(qkv_mma_kernel,
                             cudaFuncAttributeMaxDynamicSharedMemorySize, (int)sb);
        inited = true;
    }
    size_t smem_bytes = (size_t)(64 + 64 + 128 + 128) * TS * sizeof(unsigned short);

    // ---- Fork: CSR build on s2 concurrently with QKV on main stream ----
    cudaEventRecord(ev_fork, 0);
    cudaStreamWaitEvent(s2, ev_fork, 0);

    void* cptr = nullptr;
    cudaGetSymbolAddress(&cptr, g_count);
    cudaMemsetAsync(cptr, 0, (size_t)N * sizeof(int), s2);
    void* tptr = nullptr;
    cudaGetSymbolAddress(&tptr, g_total);
    cudaMemsetAsync(tptr, 0, sizeof(int), s2);
    hist_kernel<<<(E + 255) / 256, 256, 0, s2>>>(dst, E);
    assign_starts_kernel<<<(N + 255) / 256, 256, 0, s2>>>(N);
    scatter_kernel<<<(E + 255) / 256, 256, 0, s2>>>(src, dst, E);
    cudaEventRecord(ev_join, s2);

    int ntiles = (N + 63) / 64;
    dim3 qkv_grid(98, 3);
    qkv_mma_kernel<<<qkv_grid, 256, smem_bytes>>>(h, Wq, bq, Wk, bk, Wv, bv, N, ntiles);

    cudaStreamWaitEvent(0, ev_join, 0);
    gather_kernel<<<((size_t)N * 32 + 255) / 256, 256>>>(dis, att_w, att_b, out, N);
}

// round 16
// speedup vs baseline: 1.1872x; 1.0159x over previous
#include <cuda_runtime.h>
#include <cuda_bf16.h>
#include <cuda_fp16.h>
#include <math.h>

#define MAXN 50000
#define MAXE 800000
#define HD 128
#define NHEAD 8
#define TS 136   // smem tile stride in bf16 elements (272B rows: conflict-free ldmatrix)

#define QB 178   // Q blocks (3-pass)  -- one-wave partition: QB+KB+VB = 296
#define KB 59
#define VB 59

__device__ float  g_Q[(size_t)MAXN * HD];
__device__ __half g_Kh[(size_t)MAXN * HD];
__device__ __half g_Vh[(size_t)MAXN * HD];
__device__ int    g_count[MAXN];
__device__ int    g_start[MAXN];
__device__ int    g_cursor[MAXN];
__device__ int    g_csr_src[MAXE];
__device__ int    g_total[1];

// ---------------------------------------------------------------------------
// QKV projection, load-balanced single wave:
// blocks [0,QB): Q, bf16 3-pass compensated (exact scores path)
// blocks [QB,QB+KB): K, fp16 single-pass; [QB+KB,..): V, fp16 single-pass.
// W-resident; A loads before loop-top sync (overlap prior tile's MMAs).
// ---------------------------------------------------------------------------
extern __shared__ unsigned short smem_bf[];

__global__ __launch_bounds__(256, 2) void qkv_mma_kernel(
    const float* __restrict__ h,
    const float* __restrict__ Wq, const float* __restrict__ bq,
    const float* __restrict__ Wk, const float* __restrict__ bk,
    const float* __restrict__ Wv, const float* __restrict__ bv,
    int N, int ntiles)
{
    int bid = blockIdx.x;
    int proj, lb, nb;
    if (bid < QB)           { proj = 0; lb = bid;            nb = QB; }
    else if (bid < QB + KB) { proj = 1; lb = bid - QB;       nb = KB; }
    else                    { proj = 2; lb = bid - QB - KB;  nb = VB; }

    const float* W;
    const float* b;
    if (proj == 0)      { W = Wq; b = bq; }
    else if (proj == 1) { W = Wk; b = bk; }
    else                { W = Wv; b = bv; }
    const bool exact = (proj == 0);

    unsigned short* A_hi = smem_bf;                 // 64 x TS
    unsigned short* A_lo = A_hi + 64 * TS;          // 64 x TS
    unsigned short* B_hi = A_lo + 64 * TS;          // 128 x TS
    unsigned short* B_lo = B_hi + 128 * TS;         // 128 x TS

    const int tid  = threadIdx.x;
    const int warp = tid >> 5;
    const int lane = tid & 31;
    const int wm = warp & 1;
    const int wn = warp >> 1;
    const int m_base = wm * 32;
    const int n_base = wn * 32;

    // ---- Load + convert W once per block ----
    if (exact) {
        #pragma unroll
        for (int i = 0; i < 16; i++) {
            int idx = tid + i * 256;
            int r   = idx >> 5;
            int c4  = idx & 31;
            float4 v = *(const float4*)&W[(size_t)r * HD + c4 * 4];
            float vv[4] = {v.x, v.y, v.z, v.w};
            unsigned short hs[4], ls[4];
            #pragma unroll
            for (int j = 0; j < 4; j++) {
                __nv_bfloat16 hb = __float2bfloat16(vv[j]);
                float lf = vv[j] - __bfloat162float(hb);
                __nv_bfloat16 lb2 = __float2bfloat16(lf);
                hs[j] = __bfloat16_as_ushort(hb);
                ls[j] = __bfloat16_as_ushort(lb2);
            }
            uint2 ph, pl;
            ph.x = (unsigned)hs[0] | ((unsigned)hs[1] << 16);
            ph.y = (unsigned)hs[2] | ((unsigned)hs[3] << 16);
            pl.x = (unsigned)ls[0] | ((unsigned)ls[1] << 16);
            pl.y = (unsigned)ls[2] | ((unsigned)ls[3] << 16);
            *(uint2*)&B_hi[r * TS + c4 * 4] = ph;
            *(uint2*)&B_lo[r * TS + c4 * 4] = pl;
        }
    } else {
        #pragma unroll
        for (int i = 0; i < 16; i++) {
            int idx = tid + i * 256;
            int r   = idx >> 5;
            int c4  = idx & 31;
            float4 v = *(const float4*)&W[(size_t)r * HD + c4 * 4];
            uint2 p;
            __half2 h0 = __floats2half2_rn(v.x, v.y);
            __half2 h1 = __floats2half2_rn(v.z, v.w);
            p.x = *(unsigned*)&h0;
            p.y = *(unsigned*)&h1;
            *(uint2*)&B_hi[r * TS + c4 * 4] = p;
        }
    }

    const int t2 = (lane & 3) * 2;
    float2 bb[4];
    #pragma unroll
    for (int nt = 0; nt < 4; nt++) {
        int col = n_base + nt * 8 + t2;
        bb[nt].x = __ldg(&b[col]);
        bb[nt].y = __ldg(&b[col + 1]);
    }

    const int a_row  = m_base + (lane & 15);
    const int a_coff = (lane >> 4) * 8;
    const int b_roff = (lane & 7) + ((lane >> 3) & 1) * 8;
    const int b_col  = n_base + (lane >> 4) * 8;
    const int g      = lane >> 2;

    for (int tile = lb; tile < ntiles; tile += nb) {
        const int row0 = tile * 64;

        __syncthreads();

        // ---- Load h tile -> smem (split bf16 for Q; fp16 for K/V) ----
        #pragma unroll
        for (int i = 0; i < 8; i++) {
            int idx = tid + i * 256;
            int r   = idx >> 5;
            int c4  = idx & 31;
            float4 v = make_float4(0.f, 0.f, 0.f, 0.f);
            int gr = row0 + r;
            if (gr < N) v = *(const float4*)&h[(size_t)gr * HD + c4 * 4];
            if (exact) {
                float vv[4] = {v.x, v.y, v.z, v.w};
                unsigned short hs[4], ls[4];
                #pragma unroll
                for (int j = 0; j < 4; j++) {
                    __nv_bfloat16 hb = __float2bfloat16(vv[j]);
                    float lf = vv[j] - __bfloat162float(hb);
                    __nv_bfloat16 lb2 = __float2bfloat16(lf);
                    hs[j] = __bfloat16_as_ushort(hb);
                    ls[j] = __bfloat16_as_ushort(lb2);
                }
                uint2 ph, pl;
                ph.x = (unsigned)hs[0] | ((unsigned)hs[1] << 16);
                ph.y = (unsigned)hs[2] | ((unsigned)hs[3] << 16);
                pl.x = (unsigned)ls[0] | ((unsigned)ls[1] << 16);
                pl.y = (unsigned)ls[2] | ((unsigned)ls[3] << 16);
                *(uint2*)&A_hi[r * TS + c4 * 4] = ph;
                *(uint2*)&A_lo[r * TS + c4 * 4] = pl;
            } else {
                uint2 p;
                __half2 h0 = __floats2half2_rn(v.x, v.y);
                __half2 h1 = __floats2half2_rn(v.z, v.w);
                p.x = *(unsigned*)&h0;
                p.y = *(unsigned*)&h1;
                *(uint2*)&A_hi[r * TS + c4 * 4] = p;
            }
        }
        __syncthreads();

        float acc[2][4][4];
        #pragma unroll
        for (int mt = 0; mt < 2; mt++)
            #pragma unroll
            for (int nt = 0; nt < 4; nt++)
                #pragma unroll
                for (int q = 0; q < 4; q++) acc[mt][nt][q] = 0.f;

        if (exact) {
            #pragma unroll
            for (int ks = 0; ks < 8; ks++) {
                const int k0 = ks * 16;
                unsigned ah[2][4], al[2][4];
                #pragma unroll
                for (int mt = 0; mt < 2; mt++) {
                    unsigned addr = (unsigned)__cvta_generic_to_shared(
                        &A_hi[(a_row + mt * 16) * TS + k0 + a_coff]);
                    asm volatile(
                        "ldmatrix.sync.aligned.m8n8.x4.shared.b16 {%0,%1,%2,%3}, [%4];"
                        : "=r"(ah[mt][0]), "=r"(ah[mt][1]), "=r"(ah[mt][2]), "=r"(ah[mt][3])
                        : "r"(addr));
                    addr = (unsigned)__cvta_generic_to_shared(
                        &A_lo[(a_row + mt * 16) * TS + k0 + a_coff]);
                    asm volatile(
                        "ldmatrix.sync.aligned.m8n8.x4.shared.b16 {%0,%1,%2,%3}, [%4];"
                        : "=r"(al[mt][0]), "=r"(al[mt][1]), "=r"(al[mt][2]), "=r"(al[mt][3])
                        : "r"(addr));
                }
                unsigned bh[4][2], bl[4][2];
                #pragma unroll
                for (int np = 0; np < 2; np++) {
                    unsigned addr = (unsigned)__cvta_generic_to_shared(
                        &B_hi[(k0 + b_roff) * TS + b_col + np * 16]);
                    unsigned r0, r1, r2, r3;
                    asm volatile(
                        "ldmatrix.sync.aligned.m8n8.x4.trans.shared.b16 {%0,%1,%2,%3}, [%4];"
                        : "=r"(r0), "=r"(r1), "=r"(r2), "=r"(r3) : "r"(addr));
                    bh[np * 2][0] = r0; bh[np * 2][1] = r1;
                    bh[np * 2 + 1][0] = r2; bh[np * 2 + 1][1] = r3;
                    addr = (unsigned)__cvta_generic_to_shared(
                        &B_lo[(k0 + b_roff) * TS + b_col + np * 16]);
                    asm volatile(
                        "ldmatrix.sync.aligned.m8n8.x4.trans.shared.b16 {%0,%1,%2,%3}, [%4];"
                        : "=r"(r0), "=r"(r1), "=r"(r2), "=r"(r3) : "r"(addr));
                    bl[np * 2][0] = r0; bl[np * 2][1] = r1;
                    bl[np * 2 + 1][0] = r2; bl[np * 2 + 1][1] = r3;
                }
                #pragma unroll
                for (int mt = 0; mt < 2; mt++)
                    #pragma unroll
                    for (int nt = 0; nt < 4; nt++) {
                        asm volatile(
                            "mma.sync.aligned.m16n8k16.row.col.f32.bf16.bf16.f32 "
                            "{%0,%1,%2,%3}, {%4,%5,%6,%7}, {%8,%9}, {%0,%1,%2,%3};"
                            : "+f"(acc[mt][nt][0]), "+f"(acc[mt][nt][1]),
                              "+f"(acc[mt][nt][2]), "+f"(acc[mt][nt][3])
                            : "r"(ah[mt][0]), "r"(ah[mt][1]), "r"(ah[mt][2]), "r"(ah[mt][3]),
                              "r"(bh[nt][0]), "r"(bh[nt][1]));
                        asm volatile(
                            "mma.sync.aligned.m16n8k16.row.col.f32.bf16.bf16.f32 "
                            "{%0,%1,%2,%3}, {%4,%5,%6,%7}, {%8,%9}, {%0,%1,%2,%3};"
                            : "+f"(acc[mt][nt][0]), "+f"(acc[mt][nt][1]),
                              "+f"(acc[mt][nt][2]), "+f"(acc[mt][nt][3])
                            : "r"(ah[mt][0]), "r"(ah[mt][1]), "r"(ah[mt][2]), "r"(ah[mt][3]),
                              "r"(bl[nt][0]), "r"(bl[nt][1]));
                        asm volatile(
                            "mma.sync.aligned.m16n8k16.row.col.f32.bf16.bf16.f32 "
                            "{%0,%1,%2,%3}, {%4,%5,%6,%7}, {%8,%9}, {%0,%1,%2,%3};"
                            : "+f"(acc[mt][nt][0]), "+f"(acc[mt][nt][1]),
                              "+f"(acc[mt][nt][2]), "+f"(acc[mt][nt][3])
                            : "r"(al[mt][0]), "r"(al[mt][1]), "r"(al[mt][2]), "r"(al[mt][3]),
                              "r"(bh[nt][0]), "r"(bh[nt][1]));
                    }
            }
        } else {
            #pragma unroll
            for (int ks = 0; ks < 8; ks++) {
                const int k0 = ks * 16;
                unsigned ah[2][4];
                #pragma unroll
                for (int mt = 0; mt < 2; mt++) {
                    unsigned addr = (unsigned)__cvta_generic_to_shared(
                        &A_hi[(a_row + mt * 16) * TS + k0 + a_coff]);
                    asm volatile(
                        "ldmatrix.sync.aligned.m8n8.x4.shared.b16 {%0,%1,%2,%3}, [%4];"
                        : "=r"(ah[mt][0]), "=r"(ah[mt][1]), "=r"(ah[mt][2]), "=r"(ah[mt][3])
                        : "r"(addr));
                }
                unsigned bh[4][2];
                #pragma unroll
                for (int np = 0; np < 2; np++) {
                    unsigned addr = (unsigned)__cvta_generic_to_shared(
                        &B_hi[(k0 + b_roff) * TS + b_col + np * 16]);
                    unsigned r0, r1, r2, r3;
                    asm volatile(
                        "ldmatrix.sync.aligned.m8n8.x4.trans.shared.b16 {%0,%1,%2,%3}, [%4];"
                        : "=r"(r0), "=r"(r1), "=r"(r2), "=r"(r3) : "r"(addr));
                    bh[np * 2][0] = r0; bh[np * 2][1] = r1;
                    bh[np * 2 + 1][0] = r2; bh[np * 2 + 1][1] = r3;
                }
                #pragma unroll
                for (int mt = 0; mt < 2; mt++)
                    #pragma unroll
                    for (int nt = 0; nt < 4; nt++) {
                        asm volatile(
                            "mma.sync.aligned.m16n8k16.row.col.f32.f16.f16.f32 "
                            "{%0,%1,%2,%3}, {%4,%5,%6,%7}, {%8,%9}, {%0,%1,%2,%3};"
                            : "+f"(acc[mt][nt][0]), "+f"(acc[mt][nt][1]),
                              "+f"(acc[mt][nt][2]), "+f"(acc[mt][nt][3])
                            : "r"(ah[mt][0]), "r"(ah[mt][1]), "r"(ah[mt][2]), "r"(ah[mt][3]),
                              "r"(bh[nt][0]), "r"(bh[nt][1]));
                    }
            }
        }

        // ---- Epilogue: Q -> fp32, K/V -> fp16 ----
        if (exact) {
            #pragma unroll
            for (int mt = 0; mt < 2; mt++)
                #pragma unroll
                for (int half = 0; half < 2; half++) {
                    int r = row0 + m_base + mt * 16 + g + half * 8;
                    if (r < N) {
                        #pragma unroll
                        for (int nt = 0; nt < 4; nt++) {
                            int col = n_base + nt * 8 + t2;
                            float2 o;
                            o.x = acc[mt][nt][half * 2 + 0] + bb[nt].x;
                            o.y = acc[mt][nt][half * 2 + 1] + bb[nt].y;
                            *(float2*)&g_Q[(size_t)r * HD + col] = o;
                        }
                    }
                }
        } else {
            __half* outh = (proj == 1) ? g_Kh : g_Vh;
            #pragma unroll
            for (int mt = 0; mt < 2; mt++)
                #pragma unroll
                for (int half = 0; half < 2; half++) {
                    int r = row0 + m_base + mt * 16 + g + half * 8;
                    if (r < N) {
                        #pragma unroll
                        for (int nt = 0; nt < 4; nt++) {
                            int col = n_base + nt * 8 + t2;
                            float ox = acc[mt][nt][half * 2 + 0] + bb[nt].x;
                            float oy = acc[mt][nt][half * 2 + 1] + bb[nt].y;
                            *(__half2*)&outh[(size_t)r * HD + col] =
                                __floats2half2_rn(ox, oy);
                        }
                    }
                }
        }
    }
}

// ---------------------------------------------------------------------------
// CSR build
// ---------------------------------------------------------------------------
__global__ __launch_bounds__(256) void hist_kernel(const int* __restrict__ dst, int E)
{
    int e = blockIdx.x * blockDim.x + threadIdx.x;
    if (e < E) atomicAdd(&g_count[dst[e]], 1);
}

__global__ __launch_bounds__(256) void assign_starts_kernel(int N)
{
    int i = blockIdx.x * blockDim.x + threadIdx.x;
    int lane = threadIdx.x & 31;
    int c = (i < N) ? g_count[i] : 0;

    int p = c;
    #pragma unroll
    for (int off = 1; off < 32; off <<= 1) {
        int t = __shfl_up_sync(0xffffffffu, p, off);
        if (lane >= off) p += t;
    }
    int warp_total = __shfl_sync(0xffffffffu, p, 31);
    int base = 0;
    if (lane == 0) base = atomicAdd(&g_total[0], warp_total);
    base = __shfl_sync(0xffffffffu, base, 0);

    if (i < N) {
        int s = base + p - c;
        g_start[i]  = s;
        g_cursor[i] = s;
    }
}

__global__ __launch_bounds__(256) void scatter_kernel(
    const int* __restrict__ src, const int* __restrict__ dst, int E)
{
    int e = blockIdx.x * blockDim.x + threadIdx.x;
    if (e < E) {
        int pos = atomicAdd(&g_cursor[dst[e]], 1);
        g_csr_src[pos] = src[e];
    }
}

// ---------------------------------------------------------------------------
// Gather (frozen R12 shape: 4-slot ring, depth 3, .cg, one commit/iter).
// ---------------------------------------------------------------------------
__global__ __launch_bounds__(256) void gather_kernel(
    const float* __restrict__ dis,
    const float* __restrict__ att_w, const float* __restrict__ att_b,
    float* __restrict__ out, int N)
{
    __shared__ __align__(16) unsigned char kv_smem[8][4][1024];

    int wid  = threadIdx.x >> 5;
    int d    = (blockIdx.x * blockDim.x + threadIdx.x) >> 5;
    int lane = threadIdx.x & 31;
    if (d >= N) return;

    const int half = lane >> 4;
    const int sub  = lane & 15;
    const int head = sub >> 1;
    const int c0   = sub * 8;

    float4 q0 = *(const float4*)&g_Q[(size_t)d * HD + c0];
    float4 q1 = *(const float4*)&g_Q[(size_t)d * HD + c0 + 4];
    float bias = __ldg(&dis[d]) * __ldg(&att_w[head]) + __ldg(&att_b[head]);

    float a0 = 0.f, a1 = 0.f, a2 = 0.f, a3 = 0.f;
    float a4 = 0.f, a5 = 0.f, a6 = 0.f, a7 = 0.f;
    float z = 0.f;

    int start = g_start[d];
    int cnt   = g_count[d];
    int iters = (cnt + 1) >> 1;

    const unsigned lane_off = (unsigned)(half * 256 + sub * 16);

    #pragma unroll
    for (int t = 0; t < 3; t++) {
        int e = 2 * t + half;
        int s = (e < cnt) ? __ldg(&g_csr_src[start + e]) : 0;
        unsigned dst = (unsigned)__cvta_generic_to_shared(
            &kv_smem[wid][t & 3][0]) + lane_off;
        const __half* srcK = &g_Kh[(size_t)s * HD + c0];
        const __half* srcV = &g_Vh[(size_t)s * HD + c0];
        asm volatile("cp.async.cg.shared.global [%0], [%1], 16;"
                     :: "r"(dst), "l"(srcK) : "memory");
        asm volatile("cp.async.cg.shared.global [%0], [%1], 16;"
                     :: "r"(dst + 512), "l"(srcV) : "memory");
        asm volatile("cp.async.commit_group;" ::: "memory");
    }

    for (int i = 0; i < iters; i++) {
        asm volatile("cp.async.wait_group 2;" ::: "memory");
        __syncwarp();

        const unsigned char* slot = &kv_smem[wid][i & 3][0];
        uint4 Kc = *(const uint4*)(slot + lane_off);
        uint4 Vc = *(const uint4*)(slot + 512 + lane_off);
        bool v = (2 * i + half) < cnt;

        float2 k0 = __half22float2(*(const __half2*)&Kc.x);
        float2 k1 = __half22float2(*(const __half2*)&Kc.y);
        float2 k2 = __half22float2(*(const __half2*)&Kc.z);
        float2 k3 = __half22float2(*(const __half2*)&Kc.w);
        float dot = k0.x * q0.x + k0.y * q0.y + k1.x * q0.z + k1.y * q0.w
                  + k2.x * q1.x + k2.y * q1.y + k3.x * q1.z + k3.y * q1.w;
        dot += __shfl_xor_sync(0xffffffffu, dot, 1);
        float sc = (dot + bias) * 0.25f;
        sc = fminf(fmaxf(sc, -5.f), 5.f);
        float w = v ? __expf(sc) : 0.f;

        float2 v0 = __half22float2(*(const __half2*)&Vc.x);
        float2 v1 = __half22float2(*(const __half2*)&Vc.y);
        float2 v2 = __half22float2(*(const __half2*)&Vc.z);
        float2 v3 = __half22float2(*(const __half2*)&Vc.w);
        a0 += v0.x * w;  a1 += v0.y * w;
        a2 += v1.x * w;  a3 += v1.y * w;
        a4 += v2.x * w;  a5 += v2.y * w;
        a6 += v3.x * w;  a7 += v3.y * w;
        z += w;

        if (i + 3 < iters) {
            int e = 2 * (i + 3) + half;
            int s = (e < cnt) ? __ldg(&g_csr_src[start + e]) : 0;
            unsigned dst = (unsigned)__cvta_generic_to_shared(
                &kv_smem[wid][(i + 3) & 3][0]) + lane_off;
            const __half* srcK = &g_Kh[(size_t)s * HD + c0];
            const __half* srcV = &g_Vh[(size_t)s * HD + c0];
            asm volatile("cp.async.cg.shared.global [%0], [%1], 16;"
                         :: "r"(dst), "l"(srcK) : "memory");
            asm volatile("cp.async.cg.shared.global [%0], [%1], 16;"
                         :: "r"(dst + 512), "l"(srcV) : "memory");
        }
        asm volatile("cp.async.commit_group;" ::: "memory");
    }

    a0 += __shfl_xor_sync(0xffffffffu, a0, 16);
    a1 += __shfl_xor_sync(0xffffffffu, a1, 16);
    a2 += __shfl_xor_sync(0xffffffffu, a2, 16);
    a3 += __shfl_xor_sync(0xffffffffu, a3, 16);
    a4 += __shfl_xor_sync(0xffffffffu, a4, 16);
    a5 += __shfl_xor_sync(0xffffffffu, a5, 16);
    a6 += __shfl_xor_sync(0xffffffffu, a6, 16);
    a7 += __shfl_xor_sync(0xffffffffu, a7, 16);
    z  += __shfl_xor_sync(0xffffffffu, z, 16);

    if (half == 0) {
        float inv = 1.0f / z;
        float4 o0 = make_float4(a0 * inv, a1 * inv, a2 * inv, a3 * inv);
        float4 o1 = make_float4(a4 * inv, a5 * inv, a6 * inv, a7 * inv);
        *(float4*)&out[(size_t)d * HD + c0]     = o0;
        *(float4*)&out[(size_t)d * HD + c0 + 4] = o1;
    }
}

// ---------------------------------------------------------------------------
extern "C" void kernel_launch(void* const* d_in, const int* in_sizes, int n_in,
                              void* d_out, int out_size)
{
    const float* h     = (const float*)d_in[0];
    const float* dis   = (const float*)d_in[1];
    const float* Wq    = (const float*)d_in[2];
    const float* bq    = (const float*)d_in[3];
    const float* Wk    = (const float*)d_in[4];
    const float* bk    = (const float*)d_in[5];
    const float* Wv    = (const float*)d_in[6];
    const float* bv    = (const float*)d_in[7];
    const float* att_w = (const float*)d_in[8];
    const float* att_b = (const float*)d_in[9];
    const int*   src   = (const int*)d_in[10];
    const int*   dst   = (const int*)d_in[11];

    int N = in_sizes[1];
    int E = in_sizes[10];
    float* out = (float*)d_out;

    static cudaStream_t s2 = nullptr;
    static cudaEvent_t ev_fork = nullptr, ev_join = nullptr;
    static bool inited = false;
    if (!inited) {
        cudaStreamCreateWithFlags(&s2, cudaStreamNonBlocking);
        cudaEventCreateWithFlags(&ev_fork, cudaEventDisableTiming);
        cudaEventCreateWithFlags(&ev_join, cudaEventDisableTiming);
        size_t sb = (size_t)(64 + 64 + 128 + 128) * TS * sizeof(unsigned short);
        cudaFuncSetAttribute(qkv_mma_kernel,
                             cudaFuncAttributeMaxDynamicSharedMemorySize, (int)sb);
        inited = true;
    }
    size_t smem_bytes = (size_t)(64 + 64 + 128 + 128) * TS * sizeof(unsigned short);

    // ---- Fork: CSR build on s2 concurrently with QKV on main stream ----
    cudaEventRecord(ev_fork, 0);
    cudaStreamWaitEvent(s2, ev_fork, 0);

    void* cptr = nullptr;
    cudaGetSymbolAddress(&cptr, g_count);
    cudaMemsetAsync(cptr, 0, (size_t)N * sizeof(int), s2);
    void* tptr = nullptr;
    cudaGetSymbolAddress(&tptr, g_total);
    cudaMemsetAsync(tptr, 0, sizeof(int), s2);
    hist_kernel<<<(E + 255) / 256, 256, 0, s2>>>(dst, E);
    assign_starts_kernel<<<(N + 255) / 256, 256, 0, s2>>>(N);
    scatter_kernel<<<(E + 255) / 256, 256, 0, s2>>>(src, dst, E);
    cudaEventRecord(ev_join, s2);

    int ntiles = (N + 63) / 64;
    qkv_mma_kernel<<<QB + KB + VB, 256, smem_bytes>>>(
        h, Wq, bq, Wk, bk, Wv, bv, N, ntiles);

    cudaStreamWaitEvent(0, ev_join, 0);
    gather_kernel<<<((size_t)N * 32 + 255) / 256, 256>>>(dis, att_w, att_b, out, N);
}